// round 2
// baseline (speedup 1.0000x reference)
#include <cuda_runtime.h>
#include <math.h>
#include <stdint.h>

#define N_ROWS 16384
#define D_DIM  2048
#define E_DIM  64
#define BM     64
#define KB     32
#define XPAD   36          // padded x-tile row stride (floats); 144B, 16B-aligned
#define THREADS 256
#define NTILES (D_DIM / KB)                 // 64
#define STAGE_FLOATS (BM * XPAD + KB * E_DIM)  // 2304 + 2048 = 4352

__device__ __forceinline__ unsigned smem_u32(const void* p) {
    return (unsigned)__cvta_generic_to_shared(p);
}
__device__ __forceinline__ void cp_async16(unsigned dst, const void* src) {
    asm volatile("cp.async.cg.shared.global [%0], [%1], 16;\n" :: "r"(dst), "l"(src));
}
__device__ __forceinline__ void cp_commit() {
    asm volatile("cp.async.commit_group;\n");
}
__device__ __forceinline__ unsigned long long dup2(float x) {
    unsigned long long r;
    asm("mov.b64 %0, {%1, %1};" : "=l"(r) : "f"(x));
    return r;
}
__device__ __forceinline__ void fma2(unsigned long long& d, unsigned long long a,
                                     unsigned long long b) {
    asm("fma.rn.f32x2 %0, %1, %2, %0;" : "+l"(d) : "l"(a), "l"(b));
}

__global__ __launch_bounds__(THREADS)
void router_kernel(const float* __restrict__ x,
                   const float* __restrict__ W,
                   const float* __restrict__ bias,
                   float* __restrict__ out_mask,
                   float* __restrict__ out_idx,
                   int write_idx)
{
    __shared__ float smem[2 * STAGE_FLOATS];   // 34816 B; also reused for epilogue logits

    const int tid = threadIdx.x;
    const int eg  = tid & 7;        // 8 expert groups * 8 experts
    const int rg  = tid >> 3;       // 32 row groups * 2 rows
    const int r0t = rg * 2;
    const int row0 = blockIdx.x * BM;

    unsigned long long acc[2][4];
#pragma unroll
    for (int i = 0; i < 2; i++)
#pragma unroll
        for (int j = 0; j < 4; j++) acc[i][j] = 0ull;

    auto load_tile = [&](int s, int t) {
        float* sxs = smem + s * STAGE_FLOATS;
        float* sws = sxs + BM * XPAD;
        const int k0 = t * KB;
        // x tile: 64 rows x 8 float4 = 512 ops, 2 per thread
#pragma unroll
        for (int i = tid; i < BM * (KB / 4); i += THREADS) {
            int r = i >> 3, c4 = i & 7;
            cp_async16(smem_u32(sxs + r * XPAD + c4 * 4),
                       x + (size_t)(row0 + r) * D_DIM + k0 + c4 * 4);
        }
        // W tile: 32 rows x 16 float4 = 512 ops, 2 per thread
#pragma unroll
        for (int i = tid; i < KB * (E_DIM / 4); i += THREADS) {
            int kk = i >> 4, e4 = i & 15;
            cp_async16(smem_u32(sws + kk * E_DIM + e4 * 4),
                       W + (size_t)(k0 + kk) * E_DIM + e4 * 4);
        }
    };

    auto compute_tile = [&](int s) {
        const float* sxs = smem + s * STAGE_FLOATS;
        const float* sws = sxs + BM * XPAD;
#pragma unroll 8
        for (int kk = 0; kk < KB; kk++) {
            const ulonglong2* wp = (const ulonglong2*)(sws + kk * E_DIM + eg * 8);
            ulonglong2 wa = wp[0];     // experts eg*8+0..3 as 2 packed pairs
            ulonglong2 wb = wp[1];     // experts eg*8+4..7
            unsigned long long p0 = dup2(sxs[(r0t + 0) * XPAD + kk]);
            unsigned long long p1 = dup2(sxs[(r0t + 1) * XPAD + kk]);
            fma2(acc[0][0], p0, wa.x); fma2(acc[0][1], p0, wa.y);
            fma2(acc[0][2], p0, wb.x); fma2(acc[0][3], p0, wb.y);
            fma2(acc[1][0], p1, wa.x); fma2(acc[1][1], p1, wa.y);
            fma2(acc[1][2], p1, wb.x); fma2(acc[1][3], p1, wb.y);
        }
    };

    // 2-stage cp.async pipeline
    load_tile(0, 0);
    cp_commit();
    for (int t = 0; t < NTILES; t++) {
        int b = t & 1;
        if (t + 1 < NTILES) {
            load_tile(b ^ 1, t + 1);
            cp_commit();
            asm volatile("cp.async.wait_group 1;\n");
        } else {
            asm volatile("cp.async.wait_group 0;\n");
        }
        __syncthreads();
        compute_tile(b);
        __syncthreads();   // all warps done with buffer b before it is refilled
    }

    // bias + logits to smem [64][68]
    float* slog = smem;
#pragma unroll
    for (int i = 0; i < 2; i++) {
#pragma unroll
        for (int j = 0; j < 4; j++) {
            unsigned long long v = acc[i][j];
            float lo = __uint_as_float((unsigned)(v & 0xffffffffu));
            float hi = __uint_as_float((unsigned)(v >> 32));
            int e = eg * 8 + 2 * j;
            slog[(r0t + i) * 68 + e]     = lo + bias[e];
            slog[(r0t + i) * 68 + e + 1] = hi + bias[e + 1];
        }
    }
    __syncthreads();

    // epilogue: 8 warps, 8 rows each; softmax + top-2 + sparse mask
    const int wid  = tid >> 5;
    const int lane = tid & 31;
    const float NEG = -1e30f;

    for (int rr = 0; rr < 8; rr++) {
        int r = wid * 8 + rr;
        float v0 = slog[r * 68 + lane];
        float v1 = slog[r * 68 + lane + 32];

        // top-1 (tie-break: smaller index)
        float tv; int ti;
        if (v0 >= v1) { tv = v0; ti = lane; } else { tv = v1; ti = lane + 32; }
#pragma unroll
        for (int off = 16; off; off >>= 1) {
            float ov = __shfl_xor_sync(0xffffffffu, tv, off);
            int   oi = __shfl_xor_sync(0xffffffffu, ti, off);
            if (ov > tv || (ov == tv && oi < ti)) { tv = ov; ti = oi; }
        }
        float m = tv; int i1 = ti;

        // top-2: mask out i1
        float u0 = (lane == i1)        ? NEG : v0;
        float u1 = ((lane + 32) == i1) ? NEG : v1;
        if (u0 >= u1) { tv = u0; ti = lane; } else { tv = u1; ti = lane + 32; }
#pragma unroll
        for (int off = 16; off; off >>= 1) {
            float ov = __shfl_xor_sync(0xffffffffu, tv, off);
            int   oi = __shfl_xor_sync(0xffffffffu, ti, off);
            if (ov > tv || (ov == tv && oi < ti)) { tv = ov; ti = oi; }
        }
        float m2 = tv; int i2 = ti;

        // softmax denominator over all 64
        float s = expf(v0 - m) + expf(v1 - m);
#pragma unroll
        for (int off = 16; off; off >>= 1)
            s += __shfl_xor_sync(0xffffffffu, s, off);

        float g1 = 1.0f / s;
        float g2 = expf(m2 - m) / s;

        float o0 = (lane == i1)        ? g1 : ((lane == i2)        ? g2 : 0.0f);
        float o1 = ((lane + 32) == i1) ? g1 : (((lane + 32) == i2) ? g2 : 0.0f);

        size_t ro = (size_t)(row0 + r) * E_DIM;
        out_mask[ro + lane]      = o0;
        out_mask[ro + lane + 32] = o1;
        if (write_idx && lane == 0) {
            out_idx[(size_t)(row0 + r) * 2]     = (float)i1;
            out_idx[(size_t)(row0 + r) * 2 + 1] = (float)i2;
        }
    }
}

extern "C" void kernel_launch(void* const* d_in, const int* in_sizes, int n_in,
                              void* d_out, int out_size) {
    const float* x = (const float*)d_in[0];
    const float* W = (const float*)d_in[1];
    const float* b = (const float*)d_in[2];
    float* out     = (float*)d_out;
    float* out_idx = out + (size_t)N_ROWS * E_DIM;
    int write_idx  = (out_size >= N_ROWS * (E_DIM + 2)) ? 1 : 0;

    router_kernel<<<N_ROWS / BM, THREADS>>>(x, W, b, out, out_idx, write_idx);
}

// round 3
// speedup vs baseline: 2.1214x; 2.1214x over previous
#include <cuda_runtime.h>
#include <math.h>
#include <stdint.h>

#define N_ROWS 16384
#define D_DIM  2048
#define E_DIM  64
#define BM     64
#define KB     32
#define XPAD   36            // x tile row stride (floats); 144B, 16B-aligned
#define WPAD   68            // W tile row stride (floats); 272B, 16B-aligned
#define THREADS 256
#define NTILES (D_DIM / KB)  // 64
#define STAGE_FLOATS (BM * XPAD + KB * WPAD)   // 2304 + 2176 = 4480

__device__ __forceinline__ unsigned smem_u32(const void* p) {
    return (unsigned)__cvta_generic_to_shared(p);
}
__device__ __forceinline__ void cp_async16(unsigned dst, const void* src) {
    asm volatile("cp.async.cg.shared.global [%0], [%1], 16;\n" :: "r"(dst), "l"(src));
}
__device__ __forceinline__ unsigned long long dup2(float x) {
    unsigned long long r;
    asm("mov.b64 %0, {%1, %1};" : "=l"(r) : "f"(x));
    return r;
}
__device__ __forceinline__ void fma2(unsigned long long& d, unsigned long long a,
                                     unsigned long long b) {
    asm("fma.rn.f32x2 %0, %1, %2, %0;" : "+l"(d) : "l"(a), "l"(b));
}

__global__ __launch_bounds__(THREADS, 2)
void router_kernel(const float* __restrict__ x,
                   const float* __restrict__ W,
                   const float* __restrict__ bias,
                   float* __restrict__ out_mask,
                   float* __restrict__ out_idx,
                   int write_idx)
{
    __shared__ float smem[2 * STAGE_FLOATS];   // 35840 B

    const int tid  = threadIdx.x;
    const int wid  = tid >> 5;            // 8 warps; warp owns rows wid*8..+7
    const int lane = tid & 31;
    const int eg   = lane & 7;            // expert group: experts eg*8..+7
    const int kkg  = lane >> 3;           // in-warp K split: 4 groups
    const int rb   = wid * 8;             // local row base
    const int row0 = blockIdx.x * BM;

    // acc[i][j]: row rb+i, expert pair (eg*8+2j, eg*8+2j+1), partial over kk≡kkg (mod 4)
    unsigned long long acc[8][4];
#pragma unroll
    for (int i = 0; i < 8; i++)
#pragma unroll
        for (int j = 0; j < 4; j++) acc[i][j] = 0ull;

    auto load_tile = [&](int s, int t) {
        float* sxs = smem + s * STAGE_FLOATS;
        float* sws = sxs + BM * XPAD;
        const int k0 = t * KB;
        // x tile: 64 rows x 8 float4 = 512, 2 per thread
#pragma unroll
        for (int i = tid; i < BM * (KB / 4); i += THREADS) {
            int r = i >> 3, c4 = i & 7;
            cp_async16(smem_u32(sxs + r * XPAD + c4 * 4),
                       x + (size_t)(row0 + r) * D_DIM + k0 + c4 * 4);
        }
        // W tile: 32 rows x 16 float4 = 512, 2 per thread
#pragma unroll
        for (int i = tid; i < KB * (E_DIM / 4); i += THREADS) {
            int kk = i >> 4, e4 = i & 15;
            cp_async16(smem_u32(sws + kk * WPAD + e4 * 4),
                       W + (size_t)(k0 + kk) * E_DIM + e4 * 4);
        }
        asm volatile("cp.async.commit_group;\n");
    };

    auto compute_tile = [&](int s) {
        const float* sxs = smem + s * STAGE_FLOATS;
        const float* sws = sxs + BM * XPAD;
#pragma unroll
        for (int kks = 0; kks < KB / 4; kks++) {
            const int kk = kks * 4 + kkg;
            const ulonglong2* wp = (const ulonglong2*)(sws + kk * WPAD + eg * 8);
            ulonglong2 wa = wp[0];    // experts eg*8+0..3 (two packed pairs)
            ulonglong2 wb = wp[1];    // experts eg*8+4..7
#pragma unroll
            for (int i = 0; i < 8; i++) {
                unsigned long long xp = dup2(sxs[(rb + i) * XPAD + kk]);
                fma2(acc[i][0], xp, wa.x);
                fma2(acc[i][1], xp, wa.y);
                fma2(acc[i][2], xp, wb.x);
                fma2(acc[i][3], xp, wb.y);
            }
        }
    };

    load_tile(0, 0);
    for (int t = 0; t < NTILES; t++) {
        int b = t & 1;
        if (t + 1 < NTILES) {
            load_tile(b ^ 1, t + 1);
            asm volatile("cp.async.wait_group 1;\n");
        } else {
            asm volatile("cp.async.wait_group 0;\n");
        }
        __syncthreads();
        compute_tile(b);
        __syncthreads();
    }

    // reduce partial sums across the 4 kkg lane-groups (xor 8, then xor 16)
    // and add bias, write logits to smem [64][68]
    float* slog = smem;
    float bv[8];
#pragma unroll
    for (int j = 0; j < 8; j++) bv[j] = bias[eg * 8 + j];

#pragma unroll
    for (int i = 0; i < 8; i++) {
#pragma unroll
        for (int j = 0; j < 4; j++) {
            unsigned long long v = acc[i][j];
            float lo = __uint_as_float((unsigned)(v & 0xffffffffu));
            float hi = __uint_as_float((unsigned)(v >> 32));
#pragma unroll
            for (int off = 8; off <= 16; off <<= 1) {
                lo += __shfl_xor_sync(0xffffffffu, lo, off);
                hi += __shfl_xor_sync(0xffffffffu, hi, off);
            }
            if (kkg == 0) {
                int e = eg * 8 + 2 * j;
                slog[(rb + i) * WPAD + e]     = lo + bv[2 * j];
                slog[(rb + i) * WPAD + e + 1] = hi + bv[2 * j + 1];
            }
        }
    }
    __syncthreads();

    // epilogue: 8 warps, 8 rows each; softmax + top-2 + sparse mask
    const float NEG = -1e30f;
    for (int rr = 0; rr < 8; rr++) {
        int r = wid * 8 + rr;
        float v0 = slog[r * WPAD + lane];
        float v1 = slog[r * WPAD + lane + 32];

        float tv; int ti;
        if (v0 >= v1) { tv = v0; ti = lane; } else { tv = v1; ti = lane + 32; }
#pragma unroll
        for (int off = 16; off; off >>= 1) {
            float ov = __shfl_xor_sync(0xffffffffu, tv, off);
            int   oi = __shfl_xor_sync(0xffffffffu, ti, off);
            if (ov > tv || (ov == tv && oi < ti)) { tv = ov; ti = oi; }
        }
        float m = tv; int i1 = ti;

        float u0 = (lane == i1)        ? NEG : v0;
        float u1 = ((lane + 32) == i1) ? NEG : v1;
        if (u0 >= u1) { tv = u0; ti = lane; } else { tv = u1; ti = lane + 32; }
#pragma unroll
        for (int off = 16; off; off >>= 1) {
            float ov = __shfl_xor_sync(0xffffffffu, tv, off);
            int   oi = __shfl_xor_sync(0xffffffffu, ti, off);
            if (ov > tv || (ov == tv && oi < ti)) { tv = ov; ti = oi; }
        }
        float m2 = tv; int i2 = ti;

        float s = expf(v0 - m) + expf(v1 - m);
#pragma unroll
        for (int off = 16; off; off >>= 1)
            s += __shfl_xor_sync(0xffffffffu, s, off);

        float g1 = 1.0f / s;
        float g2 = expf(m2 - m) / s;

        float o0 = (lane == i1)        ? g1 : ((lane == i2)        ? g2 : 0.0f);
        float o1 = ((lane + 32) == i1) ? g1 : (((lane + 32) == i2) ? g2 : 0.0f);

        size_t ro = (size_t)(row0 + r) * E_DIM;
        out_mask[ro + lane]      = o0;
        out_mask[ro + lane + 32] = o1;
        if (write_idx && lane == 0) {
            out_idx[(size_t)(row0 + r) * 2]     = (float)i1;
            out_idx[(size_t)(row0 + r) * 2 + 1] = (float)i2;
        }
    }
}

extern "C" void kernel_launch(void* const* d_in, const int* in_sizes, int n_in,
                              void* d_out, int out_size) {
    const float* x = (const float*)d_in[0];
    const float* W = (const float*)d_in[1];
    const float* b = (const float*)d_in[2];
    float* out     = (float*)d_out;
    float* out_idx = out + (size_t)N_ROWS * E_DIM;
    int write_idx  = (out_size >= N_ROWS * (E_DIM + 2)) ? 1 : 0;

    router_kernel<<<N_ROWS / BM, THREADS>>>(x, W, b, out, out_idx, write_idx);
}

// round 7
// speedup vs baseline: 2.7159x; 1.2802x over previous
#include <cuda_runtime.h>
#include <math.h>
#include <stdint.h>

#define N_ROWS 16384
#define D_DIM  2048
#define E_DIM  64
#define BM     128
#define KT     32
#define NT     (D_DIM / KT)        // 64
#define THREADS 256
#define SXS    36                  // x tile row stride (floats), conflict-free
#define X_BYTES (BM * SXS * 4)     // 18432
#define B_BYTES (4 * 64 * 4 * 16)  // 4 k8-chunks x 64 n x 4 q x float4 = 16384
#define STAGE   (X_BYTES + B_BYTES) // 34816
#define SMEM_TOTAL (2 * STAGE + 256)
#define TAU 1e-4f
#define MAXFLAG 64

__device__ __forceinline__ uint32_t smem_u32(const void* p) {
    return (uint32_t)__cvta_generic_to_shared(p);
}
__device__ __forceinline__ void cp_async16(uint32_t dst, const void* src) {
    asm volatile("cp.async.cg.shared.global [%0], [%1], 16;\n" :: "r"(dst), "l"(src));
}
__device__ __forceinline__ uint32_t tf32_bits(float x) {
    uint32_t r;
    asm("cvt.rna.tf32.f32 %0, %1;" : "=r"(r) : "f"(x));
    return r;
}
__device__ __forceinline__ void mma_tf32(float* c, const uint32_t* a,
                                         uint32_t b0, uint32_t b1) {
    asm volatile(
        "mma.sync.aligned.m16n8k8.row.col.f32.tf32.tf32.f32 "
        "{%0,%1,%2,%3}, {%4,%5,%6,%7}, {%8,%9}, {%0,%1,%2,%3};"
        : "+f"(c[0]), "+f"(c[1]), "+f"(c[2]), "+f"(c[3])
        : "r"(a[0]), "r"(a[1]), "r"(a[2]), "r"(a[3]), "r"(b0), "r"(b1));
}

// W packed fragment-ready: [chunk c=k/8][n][q] float4 {hi(k0+q), hi(k0+q+4), lo(k0+q), lo(k0+q+4)}
__device__ float4 g_wb[256 * 64 * 4];
// exact W, K-major: g_wk[e][k]
__device__ float g_wk[E_DIM * D_DIM];

__global__ void wpack_kernel(const float* __restrict__ W) {
    int idx = blockIdx.x * blockDim.x + threadIdx.x;   // 65536
    int q = idx & 3, n = (idx >> 2) & 63, c = idx >> 8;
    int k = c * 8 + q;
    float w0 = W[(size_t)k * E_DIM + n];
    float w1 = W[(size_t)(k + 4) * E_DIM + n];
    uint32_t h0 = tf32_bits(w0), h1 = tf32_bits(w1);
    float4 v;
    v.x = __uint_as_float(h0);
    v.y = __uint_as_float(h1);
    v.z = __uint_as_float(tf32_bits(w0 - __uint_as_float(h0)));
    v.w = __uint_as_float(tf32_bits(w1 - __uint_as_float(h1)));
    g_wb[idx] = v;
    g_wk[n * D_DIM + k]     = w0;
    g_wk[n * D_DIM + k + 4] = w1;
}

__global__ __launch_bounds__(THREADS)
void router_main(const float* __restrict__ x,
                 const float* __restrict__ bias,
                 float* __restrict__ out_mask,
                 float* __restrict__ out_idx,
                 int write_idx)
{
    extern __shared__ char smem[];
    __shared__ int   s_cnt;
    __shared__ int   s_fr[MAXFLAG];
    __shared__ int4  s_fc[MAXFLAG];
    __shared__ float s_fs[MAXFLAG];
    __shared__ float s_fm[MAXFLAG];

    const uint32_t sb = smem_u32(smem);
    const int tid  = threadIdx.x;
    const int wid  = tid >> 5;
    const int lane = tid & 31;
    const int gid  = lane >> 2;      // groupID 0..7
    const int tig  = lane & 3;       // thread-in-group 0..3
    const int rb   = (wid & 3) * 32; // warp row block
    const int kh   = wid >> 2;       // K half: chunks {kh*2, kh*2+1} of each tile
    const int row0 = blockIdx.x * BM;

    if (tid < E_DIM) ((float*)(smem + 2 * STAGE))[tid] = bias[tid];
    if (tid == 0) s_cnt = 0;

    float acc[8][2][4];
#pragma unroll
    for (int j = 0; j < 8; j++)
#pragma unroll
        for (int mt = 0; mt < 2; mt++)
#pragma unroll
            for (int q = 0; q < 4; q++) acc[j][mt][q] = 0.0f;

    auto issue_loads = [&](int t) {
        const int s = t & 1;
#pragma unroll
        for (int p = 0; p < 4; p++) {               // x: 128 rows x 8 float4
            int id = tid + p * THREADS;
            int r = id >> 3, c = id & 7;
            cp_async16(sb + s * STAGE + r * (SXS * 4) + c * 16,
                       x + (size_t)(row0 + r) * D_DIM + t * KT + c * 4);
        }
#pragma unroll
        for (int p = 0; p < 4; p++) {               // B: contiguous 16KB
            int id = tid + p * THREADS;
            cp_async16(sb + s * STAGE + X_BYTES + id * 16,
                       (const char*)g_wb + (size_t)t * B_BYTES + id * 16);
        }
        asm volatile("cp.async.commit_group;\n");
    };

    auto compute_tile = [&](int s) {
        const float* sx = (const float*)(smem + s * STAGE);
        const char*  sB = smem + s * STAGE + X_BYTES;
#pragma unroll
        for (int kk = 0; kk < 2; kk++) {
            const int k8 = kh * 2 + kk;
            float4 bf[8];
#pragma unroll
            for (int j = 0; j < 8; j++)
                bf[j] = *(const float4*)(sB + k8 * 4096 + j * 512 + lane * 16);

            uint32_t ahi[2][4], alo[2][4];
#pragma unroll
            for (int mt = 0; mt < 2; mt++)
#pragma unroll
                for (int h = 0; h < 2; h++) {
                    int row = rb + mt * 16 + 8 * h + gid;
                    float xa = sx[row * SXS + k8 * 8 + tig];
                    float xb = sx[row * SXS + k8 * 8 + tig + 4];
                    uint32_t h0 = tf32_bits(xa), h1 = tf32_bits(xb);
                    ahi[mt][h]     = h0;
                    ahi[mt][h + 2] = h1;
                    alo[mt][h]     = tf32_bits(xa - __uint_as_float(h0));
                    alo[mt][h + 2] = tf32_bits(xb - __uint_as_float(h1));
                }
#pragma unroll
            for (int j = 0; j < 8; j++) {
                uint32_t bh0 = __float_as_uint(bf[j].x), bh1 = __float_as_uint(bf[j].y);
                uint32_t bl0 = __float_as_uint(bf[j].z), bl1 = __float_as_uint(bf[j].w);
#pragma unroll
                for (int mt = 0; mt < 2; mt++) {
                    mma_tf32(acc[j][mt], ahi[mt], bh0, bh1);
                    mma_tf32(acc[j][mt], ahi[mt], bl0, bl1);
                    mma_tf32(acc[j][mt], alo[mt], bh0, bh1);
                }
            }
        }
    };

    issue_loads(0);
    issue_loads(1);
    for (int t = 0; t < NT; t++) {
        if (t < NT - 1) asm volatile("cp.async.wait_group 1;\n" ::: "memory");
        else            asm volatile("cp.async.wait_group 0;\n" ::: "memory");
        __syncthreads();
        compute_tile(t & 1);
        __syncthreads();
        if (t + 2 < NT) issue_loads(t + 2);
    }

    // K-half reduction into smem logits [128][68], + bias
    float* slog = (float*)smem;
    const float* sbias = (const float*)(smem + 2 * STAGE);
    if (kh == 1) {
#pragma unroll
        for (int j = 0; j < 8; j++)
#pragma unroll
            for (int mt = 0; mt < 2; mt++) {
                int row = rb + mt * 16 + gid;
                int col = j * 8 + 2 * tig;
                slog[row * 68 + col]           = acc[j][mt][0];
                slog[row * 68 + col + 1]       = acc[j][mt][1];
                slog[(row + 8) * 68 + col]     = acc[j][mt][2];
                slog[(row + 8) * 68 + col + 1] = acc[j][mt][3];
            }
    }
    __syncthreads();
    if (kh == 0) {
#pragma unroll
        for (int j = 0; j < 8; j++)
#pragma unroll
            for (int mt = 0; mt < 2; mt++) {
                int row = rb + mt * 16 + gid;
                int col = j * 8 + 2 * tig;
                slog[row * 68 + col]           += acc[j][mt][0] + sbias[col];
                slog[row * 68 + col + 1]       += acc[j][mt][1] + sbias[col + 1];
                slog[(row + 8) * 68 + col]     += acc[j][mt][2] + sbias[col];
                slog[(row + 8) * 68 + col + 1] += acc[j][mt][3] + sbias[col + 1];
            }
    }
    __syncthreads();

    // epilogue: one thread per row; top-4 + softmax; flag near-ties
    if (tid < BM) {
        const int r = tid;
        float d[64];
#pragma unroll
        for (int e4 = 0; e4 < 16; e4++) {
            float4 v = *(const float4*)(slog + r * 68 + e4 * 4);
            d[e4 * 4] = v.x; d[e4 * 4 + 1] = v.y; d[e4 * 4 + 2] = v.z; d[e4 * 4 + 3] = v.w;
        }
        float m1 = -1e30f, m2 = -1e30f, m3 = -1e30f, m4 = -1e30f;
        int i1 = 0, i2 = 0, i3 = 0, i4 = 0;
#pragma unroll
        for (int e = 0; e < 64; e++) {
            float v = d[e];
            if (v > m1)      { m4=m3;i4=i3; m3=m2;i3=i2; m2=m1;i2=i1; m1=v;i1=e; }
            else if (v > m2) { m4=m3;i4=i3; m3=m2;i3=i2; m2=v;i2=e; }
            else if (v > m3) { m4=m3;i4=i3; m3=v;i3=e; }
            else if (v > m4) { m4=v;i4=e; }
        }
        float s = 0.0f;
#pragma unroll
        for (int e = 0; e < 64; e++) s += __expf(d[e] - m1);
        float g1 = 1.0f / s;
        float g2 = __expf(m2 - m1) / s;

        float* orow = out_mask + (size_t)(row0 + r) * E_DIM;
#pragma unroll
        for (int e4 = 0; e4 < 16; e4++) {
            float4 v;
            int e = e4 * 4;
            v.x = (e     == i1) ? g1 : ((e     == i2) ? g2 : 0.0f);
            v.y = (e + 1 == i1) ? g1 : ((e + 1 == i2) ? g2 : 0.0f);
            v.z = (e + 2 == i1) ? g1 : ((e + 2 == i2) ? g2 : 0.0f);
            v.w = (e + 3 == i1) ? g1 : ((e + 3 == i2) ? g2 : 0.0f);
            *(float4*)(orow + e) = v;
        }
        if (write_idx) {
            float2 ix = make_float2((float)i1, (float)i2);
            *(float2*)(out_idx + (size_t)(row0 + r) * 2) = ix;
        }
        if ((m1 - m2 < TAU) || (m2 - m3 < TAU) || (m3 - m4 < TAU)) {
            int f = atomicAdd(&s_cnt, 1);
            if (f < MAXFLAG) {
                s_fr[f] = r;
                s_fc[f] = make_int4(i1, i2, i3, i4);
                s_fs[f] = s;
                s_fm[f] = m1;
            }
        }
    }
    __syncthreads();

    // rescue: one warp per flagged row; recompute the 4 candidate logits exactly
    int cnt = min(s_cnt, MAXFLAG);
    for (int f = wid; f < cnt; f += 8) {
        const int r = s_fr[f];
        const int4 c = s_fc[f];
        const float sden = s_fs[f], m1a = s_fm[f];
        const float* xr = x + (size_t)(row0 + r) * D_DIM;
        float a0 = 0.f, a1 = 0.f, a2 = 0.f, a3 = 0.f;
        for (int k = lane; k < D_DIM; k += 32) {
            float xv = xr[k];
            a0 = fmaf(xv, g_wk[(size_t)c.x * D_DIM + k], a0);
            a1 = fmaf(xv, g_wk[(size_t)c.y * D_DIM + k], a1);
            a2 = fmaf(xv, g_wk[(size_t)c.z * D_DIM + k], a2);
            a3 = fmaf(xv, g_wk[(size_t)c.w * D_DIM + k], a3);
        }
#pragma unroll
        for (int off = 16; off; off >>= 1) {
            a0 += __shfl_xor_sync(0xffffffffu, a0, off);
            a1 += __shfl_xor_sync(0xffffffffu, a1, off);
            a2 += __shfl_xor_sync(0xffffffffu, a2, off);
            a3 += __shfl_xor_sync(0xffffffffu, a3, off);
        }
        // exact candidate logits (+bias), sort 4 by (value desc, index asc)
        float lv[4] = { a0 + sbias[c.x], a1 + sbias[c.y], a2 + sbias[c.z], a3 + sbias[c.w] };
        int   li[4] = { c.x, c.y, c.z, c.w };
#pragma unroll
        for (int p = 0; p < 3; p++)
#pragma unroll
            for (int q2 = 0; q2 < 3 - p; q2++) {
                bool sw = (lv[q2 + 1] > lv[q2]) ||
                          (lv[q2 + 1] == lv[q2] && li[q2 + 1] < li[q2]);
                if (sw) {
                    float tv = lv[q2]; lv[q2] = lv[q2 + 1]; lv[q2 + 1] = tv;
                    int  ti2 = li[q2]; li[q2] = li[q2 + 1]; li[q2 + 1] = ti2;
                }
            }
        float ng1 = __expf(lv[0] - m1a) / sden;
        float ng2 = __expf(lv[1] - m1a) / sden;
        int j1 = li[0], j2 = li[1];

        float* orow = out_mask + (size_t)(row0 + r) * E_DIM;
        // rewrite full row (lanes cover 64 entries, 2 each)
#pragma unroll
        for (int p = 0; p < 2; p++) {
            int e = lane + p * 32;
            orow[e] = (e == j1) ? ng1 : ((e == j2) ? ng2 : 0.0f);
        }
        if (write_idx && lane == 0) {
            float2 ix = make_float2((float)j1, (float)j2);
            *(float2*)(out_idx + (size_t)(row0 + r) * 2) = ix;
        }
    }
}

extern "C" void kernel_launch(void* const* d_in, const int* in_sizes, int n_in,
                              void* d_out, int out_size) {
    const float* x = (const float*)d_in[0];
    const float* W = (const float*)d_in[1];
    const float* b = (const float*)d_in[2];
    float* out     = (float*)d_out;
    float* out_idx = out + (size_t)N_ROWS * E_DIM;
    int write_idx  = (out_size >= N_ROWS * (E_DIM + 2)) ? 1 : 0;

    cudaFuncSetAttribute(router_main, cudaFuncAttributeMaxDynamicSharedMemorySize,
                         SMEM_TOTAL);
    wpack_kernel<<<256, 256>>>(W);
    router_main<<<N_ROWS / BM, THREADS, SMEM_TOTAL>>>(x, b, out, out_idx, write_idx);
}